// round 11
// baseline (speedup 1.0000x reference)
#include <cuda_runtime.h>
#include <cstdint>

// PairManifoldConstrainedHyperConnections — round 11: occupancy probe.
// Same direct-LDG HMMA pipeline as round 10, but 1 m16-tile (16 px) per warp
// instead of 2 -> ~70 regs -> __launch_bounds__(128,7) -> 28 warps/SM
// (vs 16 in every prior HMMA round). TPB=128 (4 warps, 64 px/CTA), grid 1024.
// k-permuted LDG.128 A-fragments, prebuilt permuted bf16 B-fragments,
// register double buffer, warp-private mainloop, no barriers.

#define TPB 128
#define DP  28   // D staging pitch (floats)

typedef unsigned long long ull;

__device__ ull wfrag_g[3072];                   // [32 kstep][3 ntile][32 lane]

__device__ __forceinline__ uint32_t bf16x2(float lo, float hi){
    uint32_t r; asm("cvt.rn.bf16x2.f32 %0, %1, %2;" : "=r"(r) : "f"(hi), "f"(lo)); return r;
}
__device__ __forceinline__ ull fma2(ull a, ull b, ull c){
    ull d; asm("fma.rn.f32x2 %0, %1, %2, %3;" : "=l"(d) : "l"(a), "l"(b), "l"(c)); return d;
}
__device__ __forceinline__ float lo2(ull v){ return __uint_as_float((unsigned)(v & 0xffffffffull)); }
__device__ __forceinline__ float hi2(ull v){ return __uint_as_float((unsigned)(v >> 32)); }
__device__ __forceinline__ float tanh_a(float x){ float y; asm("tanh.approx.f32 %0, %1;" : "=f"(y) : "f"(x)); return y; }
__device__ __forceinline__ float rcp_a(float x){ float y; asm("rcp.approx.f32 %0, %1;" : "=f"(y) : "f"(x)); return y; }
__device__ __forceinline__ float ex2_a(float x){ float y; asm("ex2.approx.f32 %0, %1;" : "=f"(y) : "f"(x)); return y; }
__device__ __forceinline__ float exp_a(float x){ return ex2_a(x * 1.4426950408889634f); }

__device__ __forceinline__ void mma_bf16(float* d, uint32_t a0, uint32_t a1,
                                         uint32_t a2, uint32_t a3,
                                         uint32_t b0, uint32_t b1){
    asm volatile(
        "mma.sync.aligned.m16n8k16.row.col.f32.bf16.bf16.f32 "
        "{%0,%1,%2,%3}, {%4,%5,%6,%7}, {%8,%9}, {%0,%1,%2,%3};"
        : "+f"(d[0]), "+f"(d[1]), "+f"(d[2]), "+f"(d[3])
        : "r"(a0), "r"(a1), "r"(a2), "r"(a3), "r"(b0), "r"(b1));
}

// ---- init: fragment-ready bf16 weights, k-permuted to match LDG.128 A-frags.
__global__ void pmchc_init(const float* __restrict__ wpre,
                           const float* __restrict__ wpost,
                           const float* __restrict__ wres)
{
    int i = blockIdx.x * blockDim.x + threadIdx.x;
    if (i >= 3072) return;
    int lane = i & 31, nt = (i >> 5) % 3, s = i / 96;
    int j = nt * 8 + (lane >> 2);
    int k0 = s * 16 + (lane & 3) * 4;
    const float* wr = (j < 4) ? wpre + j * 512
                    : (j < 8) ? wpost + (j - 4) * 512
                              : wres + (j - 8) * 512;
    float4 v = *(const float4*)(wr + k0);
    wfrag_g[i] = (ull)bf16x2(v.x, v.y) | ((ull)bf16x2(v.z, v.w) << 32);
}

__global__ void __launch_bounds__(TPB, 7)
pmchc_hmma(const float* __restrict__ x,
           const float* __restrict__ bpre,
           const float* __restrict__ bpost,
           const float* __restrict__ bres,
           const float* __restrict__ apre,
           const float* __restrict__ apost,
           const float* __restrict__ ares,
           float* __restrict__ out)
{
    __shared__ float dstage[64 * DP];
    __shared__ float sssm[64];

    const int t = threadIdx.x, w = t >> 5, l = t & 31;
    const int gr = l >> 2, q = l & 3, c2 = q * 2;
    const int pxbase = blockIdx.x * 64;

    // warp w owns 16 px: rows [w*16, w*16+16)
    const float* gx = x + (size_t)(pxbase + w * 16) * 512 + q * 4;
    const float* rp0 = gx + (size_t)(gr)     * 512;   // rows 0..7  (c0/c1 half)
    const float* rp1 = gx + (size_t)(gr + 8) * 512;   // rows 8..15 (c2/c3 half)

    float acc[12];
    ull ssq[2];
    ssq[0] = ssq[1] = 0ull;
#pragma unroll
    for (int j = 0; j < 12; j++) acc[j] = 0.f;

    // buf[parity][kk*2 + half]
    float4 buf[2][4];
#pragma unroll
    for (int kk = 0; kk < 2; kk++) {
        buf[0][kk * 2]     = *(const float4*)(rp0 + kk * 16);
        buf[0][kk * 2 + 1] = *(const float4*)(rp1 + kk * 16);
    }

#pragma unroll 2
    for (int ch = 0; ch < 16; ch++) {
        const int cur = ch & 1, nxt = cur ^ 1;
        if (ch < 15) {
            const int o = (ch + 1) * 32;
#pragma unroll
            for (int kk = 0; kk < 2; kk++) {
                buf[nxt][kk * 2]     = *(const float4*)(rp0 + o + kk * 16);
                buf[nxt][kk * 2 + 1] = *(const float4*)(rp1 + o + kk * 16);
            }
        }
#pragma unroll
        for (int kk = 0; kk < 2; kk++) {
            const int ks = ch * 2 + kk;
            ull B0 = __ldg(&wfrag_g[(ks * 3 + 0) * 32 + l]);
            ull B1 = __ldg(&wfrag_g[(ks * 3 + 1) * 32 + l]);
            ull B2 = __ldg(&wfrag_g[(ks * 3 + 2) * 32 + l]);
            float4 vA = buf[cur][kk * 2];
            float4 vB = buf[cur][kk * 2 + 1];
            ull a01 = *(const ull*)&vA.x, a23 = *(const ull*)&vA.z;
            ull b01 = *(const ull*)&vB.x, b23 = *(const ull*)&vB.z;
            ssq[0] = fma2(a01, a01, fma2(a23, a23, ssq[0]));
            ssq[1] = fma2(b01, b01, fma2(b23, b23, ssq[1]));
            uint32_t a0 = bf16x2(vA.x, vA.y);
            uint32_t a2 = bf16x2(vA.z, vA.w);
            uint32_t a1 = bf16x2(vB.x, vB.y);
            uint32_t a3 = bf16x2(vB.z, vB.w);
            mma_bf16(acc + 0, a0, a1, a2, a3, (uint32_t)B0, (uint32_t)(B0 >> 32));
            mma_bf16(acc + 4, a0, a1, a2, a3, (uint32_t)B1, (uint32_t)(B1 >> 32));
            mma_bf16(acc + 8, a0, a1, a2, a3, (uint32_t)B2, (uint32_t)(B2 >> 32));
        }
    }

    // ---- per-pixel ss: combine packed halves, reduce over quad lanes ----
#pragma unroll
    for (int h = 0; h < 2; h++) {
        float s = lo2(ssq[h]) + hi2(ssq[h]);
        s += __shfl_xor_sync(0xffffffffu, s, 1);
        s += __shfl_xor_sync(0xffffffffu, s, 2);
        if (q == 0)
            sssm[w * 16 + h * 8 + gr] = s;
    }

    // ---- stage D (warp-private 16 rows) ----
    float* dw = dstage + w * 16 * DP;
#pragma unroll
    for (int nt = 0; nt < 3; nt++) {
        int col = nt * 8 + c2;
        *(float2*)(dw + (gr)     * DP + col) = make_float2(acc[nt*4+0], acc[nt*4+1]);
        *(float2*)(dw + (gr + 8) * DP + col) = make_float2(acc[nt*4+2], acc[nt*4+3]);
    }
    __syncwarp();

    // ---- epilogue: lanes 0..15 take one px each ----
    if (l < 16) {
        const float a_pre = __ldg(apre), a_post = __ldg(apost), a_res = __ldg(ares);

        float dv[24];
        const float4* drd = (const float4*)(dw + l * DP);
#pragma unroll
        for (int qq = 0; qq < 6; qq++) ((float4*)dv)[qq] = drd[qq];

        float sc = rsqrtf(sssm[w * 16 + l] * (1.0f / 512.0f) + 1.1920929e-07f);
#pragma unroll
        for (int j = 0; j < 24; j++) dv[j] *= sc;

        float4 o0, o1;
        float* po0 = (float*)&o0;
        float* po1 = (float*)&o1;
#pragma unroll
        for (int j = 0; j < 4; j++) {
            po0[j] =        rcp_a(1.0f + exp_a(-(a_pre  * tanh_a(dv[j])     + __ldg(bpre + j))));
            po1[j] = 2.0f * rcp_a(1.0f + exp_a(-(a_post * tanh_a(dv[4 + j]) + __ldg(bpost + j))));
        }

        float M[16];
#pragma unroll
        for (int k = 0; k < 16; k++) M[k] = exp_a(a_res * tanh_a(dv[8 + k]) + __ldg(bres + k));

#pragma unroll 1
        for (int it = 0; it < 20; it++) {
#pragma unroll
            for (int i = 0; i < 4; i++) {
                float r = rcp_a(M[i*4] + M[i*4+1] + M[i*4+2] + M[i*4+3]);
                M[i*4] *= r; M[i*4+1] *= r; M[i*4+2] *= r; M[i*4+3] *= r;
            }
#pragma unroll
            for (int j = 0; j < 4; j++) {
                float r = rcp_a(M[j] + M[4+j] + M[8+j] + M[12+j]);
                M[j] *= r; M[4+j] *= r; M[8+j] *= r; M[12+j] *= r;
            }
        }

        float4* o4 = (float4*)(out + (size_t)(pxbase + w * 16 + l) * 24);
        o4[0] = o0;
        o4[1] = o1;
#pragma unroll
        for (int i = 0; i < 4; i++)
            o4[2 + i] = make_float4(M[i*4], M[i*4+1], M[i*4+2], M[i*4+3]);
    }
}

extern "C" void kernel_launch(void* const* d_in, const int* in_sizes, int n_in,
                              void* d_out, int out_size)
{
    const float* x     = (const float*)d_in[0];
    const float* wpre  = (const float*)d_in[1];
    const float* wpost = (const float*)d_in[2];
    const float* wres  = (const float*)d_in[3];
    const float* bpre  = (const float*)d_in[4];
    const float* bpost = (const float*)d_in[5];
    const float* bres  = (const float*)d_in[6];
    const float* apre  = (const float*)d_in[7];
    const float* apost = (const float*)d_in[8];
    const float* ares  = (const float*)d_in[9];
    float* out = (float*)d_out;

    int px = in_sizes[0] / 512;    // 65536
    int blocks = px / 64;          // 1024

    pmchc_init<<<24, 128>>>(wpre, wpost, wres);
    pmchc_hmma<<<blocks, TPB>>>(x, bpre, bpost, bres,
                                apre, apost, ares, out);
}